// round 6
// baseline (speedup 1.0000x reference)
#include <cuda_runtime.h>

// Fused autoencoder forward + Jacobians.
// 1 sample/thread; f32x2-packed across unit pairs (forward z, output accs)
// and across the 2 tangent columns. All weights pre-packed into __constant__
// in multiple layouts by a prep kernel (LDCU/uniform operands keep FFMA2 at
// rt=2 on the fma pipe).
// Outputs: theta[N,2] | J_h[N,2,2] | q_hat[N,2] | J_h_dec[N,2,2] | J_h_ana[N,2,2]

typedef unsigned long long pf;   // packed (lo,hi) f32 pair

struct CData {
    float2 w2p[2][128];  // [m*16+i] = (w2[2m][i], w2[2m+1][i])   (z pair layout)
    float2 w2d[2][256];  // [j*16+i] = dup w2[j][i]               (tangent layout)
    float2 w3p[2][16];   // [j]      = (w3[0][j], w3[1][j])       (acc pair)
    float2 w3d[2][32];   // [r*16+j] = dup w3[r][j]               (jacobian rows)
    float2 w1c[2][16];   // [2k]=(w1[2k][0],w1[2k+1][0]), [2k+1]=(w1[2k][1],w1[2k+1][1])
    float2 w1p[2][16];   // [i]      = (w1[i][0], w1[i][1])       (tangent init)
    float2 b1p[2][8];    // (b1[2k], b1[2k+1])
    float2 b2p[2][8];
    float2 b3p[2];       // (b3[0], b3[1])
};

__constant__ CData CW;
__device__   CData g_scratch;

union PU { pf u; float2 f; };

__device__ __forceinline__ pf pk(float2 v)      { PU c; c.f = v; return c.u; }
__device__ __forceinline__ pf dup2(float v)     { PU c; c.f = make_float2(v, v); return c.u; }
__device__ __forceinline__ float2 upk(pf u)     { PU c; c.u = u; return c.f; }
__device__ __forceinline__ pf ffma2(pf a, pf b, pf c) {
    pf d; asm("fma.rn.f32x2 %0, %1, %2, %3;" : "=l"(d) : "l"(a), "l"(b), "l"(c)); return d;
}
__device__ __forceinline__ pf fmul2(pf a, pf b) {
    pf d; asm("mul.rn.f32x2 %0, %1, %2;" : "=l"(d) : "l"(a), "l"(b)); return d;
}

// softplus h and sigmoid s (stable, 3 MUFU)
__device__ __forceinline__ void act(float z, float& h, float& s) {
    const float L2E = 1.442695041f, LN2 = 0.6931471806f;
    float t, g;
    asm("ex2.approx.ftz.f32 %0, %1;" : "=f"(t) : "f"(fabsf(z) * -L2E));
    asm("lg2.approx.ftz.f32 %0, %1;" : "=f"(g) : "f"(1.0f + t));
    h = fmaf(g, LN2, fmaxf(z, 0.0f));
    asm("ex2.approx.ftz.f32 %0, %1;" : "=f"(s) : "f"(fmaf(fminf(z, 0.0f), L2E, -g)));
}

// MLP 2->16->16->2 softplus. x packed pairs; returns y=(y0,y1) packed and
// Jacobian rows rj0=(J00,J01), rj1=(J10,J11) packed.
template<int E>
__device__ __forceinline__ void mlp_jac(float x0, float x1,
                                        pf& y, pf& rj0, pf& rj1)
{
    const pf x0d = dup2(x0);
    const pf x1d = dup2(x1);

    pf hd[16];    // (h,h) duplicated
    pf tab[16];   // (ta,tb)
#pragma unroll
    for (int k = 0; k < 8; ++k) {
        pf zp = ffma2(pk(CW.w1c[E][2*k]), x0d,
                 ffma2(pk(CW.w1c[E][2*k+1]), x1d, pk(CW.b1p[E][k])));
        float2 z = upk(zp);
        float h0, s0, h1, s1;
        act(z.x, h0, s0);
        act(z.y, h1, s1);
        hd[2*k]   = dup2(h0);
        hd[2*k+1] = dup2(h1);
        tab[2*k]   = fmul2(dup2(s0), pk(CW.w1p[E][2*k]));
        tab[2*k+1] = fmul2(dup2(s1), pk(CW.w1p[E][2*k+1]));
    }

    pf acc = pk(CW.b3p[E]);          // (y0,y1)
    pf j0 = 0, j1 = 0;               // (J00,J01), (J10,J11)
#pragma unroll
    for (int m = 0; m < 8; ++m) {    // j-pair (2m, 2m+1)
        pf zp = pk(CW.b2p[E][m]);
        pf ab0 = 0, ab1 = 0;
#pragma unroll
        for (int i = 0; i < 16; ++i) {
            zp  = ffma2(pk(CW.w2p[E][16*m + i]), hd[i], zp);
            ab0 = ffma2(pk(CW.w2d[E][16*(2*m) + i]),   tab[i], ab0);
            ab1 = ffma2(pk(CW.w2d[E][16*(2*m+1) + i]), tab[i], ab1);
        }
        float2 z = upk(zp);
        float h0, s0, h1, s1;
        act(z.x, h0, s0);
        act(z.y, h1, s1);
        pf sab0 = fmul2(dup2(s0), ab0);
        pf sab1 = fmul2(dup2(s1), ab1);
        acc = ffma2(pk(CW.w3p[E][2*m]),   dup2(h0), acc);
        acc = ffma2(pk(CW.w3p[E][2*m+1]), dup2(h1), acc);
        j0 = ffma2(pk(CW.w3d[E][2*m]),        sab0, j0);
        j1 = ffma2(pk(CW.w3d[E][16 + 2*m]),   sab0, j1);
        j0 = ffma2(pk(CW.w3d[E][2*m+1]),      sab1, j0);
        j1 = ffma2(pk(CW.w3d[E][16 + 2*m+1]), sab1, j1);
    }
    y = acc; rj0 = j0; rj1 = j1;
}

__global__ void __launch_bounds__(256) prep_kernel(
    const float* __restrict__ ew1, const float* __restrict__ eb1,
    const float* __restrict__ ew2, const float* __restrict__ eb2,
    const float* __restrict__ ew3, const float* __restrict__ eb3,
    const float* __restrict__ dw1, const float* __restrict__ db1,
    const float* __restrict__ dw2, const float* __restrict__ db2,
    const float* __restrict__ dw3, const float* __restrict__ db3)
{
    const int t = threadIdx.x;
    const float* W1[2] = {ew1, dw1};
    const float* B1[2] = {eb1, db1};
    const float* W2[2] = {ew2, dw2};
    const float* B2[2] = {eb2, db2};
    const float* W3[2] = {ew3, dw3};
    const float* B3[2] = {eb3, db3};

#pragma unroll
    for (int E = 0; E < 2; ++E) {
        // w2d: dup, 256 entries
        g_scratch.w2d[E][t] = make_float2(W2[E][t], W2[E][t]);
        // w2p: 128 entries
        if (t < 128) {
            int m = t / 16, i = t % 16;
            g_scratch.w2p[E][t] =
                make_float2(W2[E][(2*m)*16 + i], W2[E][(2*m+1)*16 + i]);
        }
        if (t < 32) g_scratch.w3d[E][t] = make_float2(W3[E][t], W3[E][t]);
        if (t < 16) {
            g_scratch.w3p[E][t] = make_float2(W3[E][t], W3[E][16 + t]);
            g_scratch.w1p[E][t] = make_float2(W1[E][2*t], W1[E][2*t + 1]);
        }
        if (t < 8) {
            g_scratch.w1c[E][2*t]   = make_float2(W1[E][4*t],     W1[E][4*t + 2]);
            g_scratch.w1c[E][2*t+1] = make_float2(W1[E][4*t + 1], W1[E][4*t + 3]);
            g_scratch.b1p[E][t] = make_float2(B1[E][2*t], B1[E][2*t + 1]);
            g_scratch.b2p[E][t] = make_float2(B2[E][2*t], B2[E][2*t + 1]);
        }
        if (t == 0) g_scratch.b3p[E] = make_float2(B3[E][0], B3[E][1]);
    }
}

__global__ void __launch_bounds__(256) ae_kernel(
    const float* __restrict__ q, float* __restrict__ out, int N)
{
    const int n = blockIdx.x * 256 + threadIdx.x;
    if (n >= N) return;

    const float2 qv = reinterpret_cast<const float2*>(q)[n];
    const float q0 = qv.x, q1 = qv.y;

    // analytic jacobian
    const float r2  = fmaf(q0, q0, q1 * q1);
    const float inv = __fdividef(1.0f, r2);
    const float isr = rsqrtf(r2 + 1e-8f);
    const float ja00 = -q1 * inv;
    const float ja01 =  q0 * inv;
    const float ja10 =  q0 * isr;
    const float ja11 =  q1 * isr;

    pf th, jh0, jh1, qh, jd0, jd1;
    mlp_jac<0>(q0, q1, th, jh0, jh1);
    float2 thf = upk(th);
    mlp_jac<1>(thf.x, thf.y, qh, jd0, jd1);

    const size_t Ns = (size_t)N;
    pf*     o_theta = reinterpret_cast<pf*>(out);
    pf*     o_jh    = reinterpret_cast<pf*>(out + 2 * Ns);
    pf*     o_qhat  = reinterpret_cast<pf*>(out + 6 * Ns);
    pf*     o_jd    = reinterpret_cast<pf*>(out + 8 * Ns);
    float4* o_ja    = reinterpret_cast<float4*>(out + 12 * Ns);

    o_theta[n]      = th;
    o_jh[2 * n]     = jh0;
    o_jh[2 * n + 1] = jh1;
    o_qhat[n]       = qh;
    o_jd[2 * n]     = jd0;
    o_jd[2 * n + 1] = jd1;
    o_ja[n]         = make_float4(ja00, ja01, ja10, ja11);
}

extern "C" void kernel_launch(void* const* d_in, const int* in_sizes, int n_in,
                              void* d_out, int out_size) {
    const float* q = (const float*)d_in[0];

    prep_kernel<<<1, 256>>>(
        (const float*)d_in[1], (const float*)d_in[2],
        (const float*)d_in[3], (const float*)d_in[4],
        (const float*)d_in[5], (const float*)d_in[6],
        (const float*)d_in[7], (const float*)d_in[8],
        (const float*)d_in[9], (const float*)d_in[10],
        (const float*)d_in[11], (const float*)d_in[12]);

    void* cw_addr = nullptr;
    void* sc_addr = nullptr;
    cudaGetSymbolAddress(&cw_addr, CW);
    cudaGetSymbolAddress(&sc_addr, g_scratch);
    cudaMemcpyAsync(cw_addr, sc_addr, sizeof(CData),
                    cudaMemcpyDeviceToDevice, 0);

    const int N = in_sizes[0] / 2;
    const int blocks = (N + 255) / 256;
    ae_kernel<<<blocks, 256>>>(q, (float*)d_out, N);
}